// round 6
// baseline (speedup 1.0000x reference)
#include <cuda_runtime.h>
#include <cuda_bf16.h>
#include <cstdint>

// Unfold3d: x (B=4, C=32, D=16, H=48, W=48) fp32, K=3, PAD=1, STR=1, DIL=1.
// out[b][c*27 + kidx][d*HW + h*W + w] = x[b][c][d+kd-1][h+kh-1][w+kw-1] (0 OOB)
//
// R6: DRAM write-locality fix. Loop order changed to (kd,kh) OUTER, row-slab
// INNER: each CTA writes a channel's full contiguous 9KB slice before moving
// to the next channel (R4/R5 interleaved 3KB chunks across all 27 channels,
// ~30K active scattered write streams -> row-buffer thrash). Read path is the
// R4 branch-free haloed-smem variant (2 aligned LDS.128 per 3 stores, zero
// predication). __stcs streaming stores.

#define B_  4
#define C_  32
#define D_  16
#define H_  48
#define W_  48
#define HW  (H_ * W_)          // 2304
#define DHW (D_ * HW)          // 36864
#define W4  (W_ / 4)           // 12

#define SH  (H_ + 2)           // 50 padded rows
#define SW  52                 // padded row stride (floats), 16B-aligned
#define SPLANE (SH * SW)       // 2600 (16B-aligned)
#define SMEM_FLOATS (3 * SPLANE)  // 7800 floats = 31200 B

__global__ __launch_bounds__(192, 7) void unfold3d_kernel(
    const float* __restrict__ x, float* __restrict__ out)
{
    __shared__ float s[SMEM_FLOATS];

    const int d  = blockIdx.x;          // 0..15
    const int bc = blockIdx.y;          // 0..127

    const int w4 = threadIdx.x;         // 0..11
    const int hb = threadIdx.y;         // 0..15
    const int tid = hb * 12 + w4;       // 0..191

    // ---- Phase 0: zero-fill smem (vectorized) ----
    {
        float4* s4 = reinterpret_cast<float4*>(s);
        const int n4 = SMEM_FLOATS / 4;             // 1950
        #pragma unroll
        for (int k = 0; k < (n4 + 191) / 192; k++) {
            int i = tid + k * 192;
            if (i < n4) s4[i] = make_float4(0.f, 0.f, 0.f, 0.f);
        }
    }
    __syncthreads();

    // ---- Phase 1: load 3 planes (d-1, d, d+1) into haloed smem ----
    {
        const float* __restrict__ xb = x + (size_t)bc * DHW;
        #pragma unroll
        for (int p = 0; p < 3; p++) {
            const int dd = d + p - 1;
            if ((unsigned)dd < (unsigned)D_) {
                const float* __restrict__ plane = xb + dd * HW;
                float* __restrict__ sp = s + p * SPLANE;
                #pragma unroll
                for (int k = 0; k < 3; k++) {
                    const int row = hb + k * 16;            // 0..47
                    float4 g = *reinterpret_cast<const float4*>(
                        plane + row * W_ + w4 * 4);
                    float* dst = sp + (row + 1) * SW + 1 + w4 * 4;
                    dst[0] = g.x; dst[1] = g.y; dst[2] = g.z; dst[3] = g.w;
                }
            }
        }
    }
    __syncthreads();

    // ---- Phase 2: channel-sequential stores ----
    // (kd,kh) outer -> the block finishes the full 48x48 slice of each of the
    // 3 kw-channels before advancing; every channel slice is written exactly
    // once, in one contiguous 9KB pass.
    float* __restrict__ ob = out + (size_t)bc * 27 * DHW + (size_t)d * HW;

    #pragma unroll
    for (int kd = 0; kd < 3; kd++) {
        #pragma unroll
        for (int kh = 0; kh < 3; kh++) {
            const float* __restrict__ sp = s + kd * SPLANE + kh * SW + w4 * 4;
            float* __restrict__ och = ob + ((kd * 3 + kh) * 3) * DHW + w4 * 4;

            #pragma unroll
            for (int k = 0; k < 3; k++) {
                const int h = hb + k * 16;                  // 0..47
                const float* __restrict__ p = sp + h * SW;
                // q0 = padded cols [4w4 .. 4w4+3] (input cols 4w4-1 .. 4w4+2)
                float4 q0 = *reinterpret_cast<const float4*>(p);
                float4 q1 = *reinterpret_cast<const float4*>(p + 4);

                float* o = och + h * W_;
                __stcs(reinterpret_cast<float4*>(o), q0);            // kw=0
                __stcs(reinterpret_cast<float4*>(o + DHW),
                       make_float4(q0.y, q0.z, q0.w, q1.x));         // kw=1
                __stcs(reinterpret_cast<float4*>(o + 2 * DHW),
                       make_float4(q0.z, q0.w, q1.x, q1.y));         // kw=2
            }
        }
    }
}

extern "C" void kernel_launch(void* const* d_in, const int* in_sizes, int n_in,
                              void* d_out, int out_size)
{
    const float* x = (const float*)d_in[0];
    float* out = (float*)d_out;

    dim3 grid(D_, B_ * C_);        // 16 x 128 = 2048 blocks
    dim3 block(W4, 16);            // 192 threads
    unfold3d_kernel<<<grid, block>>>(x, out);
}